// round 4
// baseline (speedup 1.0000x reference)
#include <cuda_runtime.h>
#include <math.h>
#include <stdint.h>

#define BB 8
#define TT 2048
#define SS 2048
#define DD 256
#define NCHUNK 16
#define TCH 128   /* TT / NCHUNK */
#define NSBLK 16  /* SS / 128 */

// ---------------- scratch (device globals; no runtime allocation) ----------------
__device__ float        g_align [(size_t)BB * TT * SS]; // e_blk, then unnormalized u in place
__device__ float        g_bmax  [BB * TT * NSBLK];      // per (row, s-block) local max
__device__ unsigned int g_rowmax[BB * TT];              // monotone-uint encoded global row max
__device__ float        g_carry [BB * NCHUNK * SS];     // per-chunk column sums -> exclusive prefix
__device__ float        g_partial[(size_t)BB * TT * 64];// per (row, sblk*8+warp) partial rowsums
__device__ float        g_invsum[BB * TT];              // 1 / rowsum
__device__ float        g_c     [(size_t)BB * TT * DD]; // context vectors (16MB)

// ---------------- helpers ----------------
__device__ __forceinline__ void ffma2(unsigned long long& d, unsigned long long a, unsigned long long b) {
    asm("fma.rn.f32x2 %0, %1, %2, %0;" : "+l"(d) : "l"(a), "l"(b));
}
__device__ __forceinline__ unsigned long long fdup(float x) {
    unsigned long long r;
    asm("mov.b64 %0, {%1, %1};" : "=l"(r) : "f"(x));
    return r;
}
__device__ __forceinline__ float lo32(unsigned long long v) { return __uint_as_float((unsigned)(v & 0xffffffffull)); }
__device__ __forceinline__ float hi32(unsigned long long v) { return __uint_as_float((unsigned)(v >> 32)); }

__device__ __forceinline__ unsigned fenc(float f) {
    unsigned u = __float_as_uint(f);
    return (u & 0x80000000u) ? ~u : (u | 0x80000000u);
}
__device__ __forceinline__ float fdec(unsigned e) {
    return (e & 0x80000000u) ? __uint_as_float(e ^ 0x80000000u) : __uint_as_float(~e);
}

// dtype-robust length decode (jax may hand us int32 despite int64 in reference)
__device__ __forceinline__ int decode_len(const int* __restrict__ lens32, int b) {
    bool is64 = (lens32[1] == 0) && (lens32[3] == 0) && (lens32[5] == 0) && (lens32[7] == 0);
    if (is64) return (int)((const long long*)lens32)[b];
    return lens32[b];
}

// packed 8x8 f32x2 outer-product step (A pre-duplicated in smem)
__device__ __forceinline__ void mma_step_p(const unsigned long long* __restrict__ As_k,
                                           const float* __restrict__ Bs_k,
                                           int ty8, int tx8,
                                           unsigned long long acc[8][4]) {
    ulonglong2 a01 = *(const ulonglong2*)(As_k + ty8);
    ulonglong2 a23 = *(const ulonglong2*)(As_k + ty8 + 2);
    ulonglong2 a45 = *(const ulonglong2*)(As_k + ty8 + 4);
    ulonglong2 a67 = *(const ulonglong2*)(As_k + ty8 + 6);
    unsigned long long a[8] = {a01.x, a01.y, a23.x, a23.y, a45.x, a45.y, a67.x, a67.y};
    const ulonglong2* bp = (const ulonglong2*)(Bs_k + tx8);
    ulonglong2 b01 = bp[0], b23 = bp[1];
#pragma unroll
    for (int i = 0; i < 8; ++i) {
        ffma2(acc[i][0], a[i], b01.x);
        ffma2(acc[i][1], a[i], b01.y);
        ffma2(acc[i][2], a[i], b23.x);
        ffma2(acc[i][3], a[i], b23.y);
    }
}

// ---------------- init ----------------
__global__ void k_init() {
    int i = blockIdx.x * blockDim.x + threadIdx.x;
    if (i < BB * TT) g_rowmax[i] = 0x007FFFFFu;  // fenc(-inf)
}

// ---------------- GEMM1: logits -> block max -> e_blk = exp(v - m_blk) ----------------
__global__ void __launch_bounds__(256) k_gemm1(const float* __restrict__ src,
                                               const float* __restrict__ mb,
                                               const int* __restrict__ lens32) {
    __shared__ __align__(16) unsigned long long As2[2][8][128];
    __shared__ __align__(16) float              Bs [2][8][132];
    __shared__ float red[128][17];

    const int tid = threadIdx.x;
    const int tx = tid & 15, ty = tid >> 4;
    const int bz = blockIdx.z;
    const int t0 = blockIdx.y * 128;
    const int s0 = blockIdx.x * 128;

    const float* A  = src + (size_t)bz * TT * DD;
    const float* Bm = mb  + (size_t)bz * SS * DD;

    const int row = tid >> 1;           // 0..127
    const int c4  = (tid & 1) * 4;      // 0 or 4

    float4 pa = *(const float4*)(A  + (size_t)(t0 + row) * DD + c4);
    float4 pb = *(const float4*)(Bm + (size_t)(s0 + row) * DD + c4);
    {
        As2[0][c4 + 0][row] = fdup(pa.x); As2[0][c4 + 1][row] = fdup(pa.y);
        As2[0][c4 + 2][row] = fdup(pa.z); As2[0][c4 + 3][row] = fdup(pa.w);
        Bs[0][c4 + 0][row] = pb.x; Bs[0][c4 + 1][row] = pb.y;
        Bs[0][c4 + 2][row] = pb.z; Bs[0][c4 + 3][row] = pb.w;
    }
    __syncthreads();

    unsigned long long acc[8][4];
#pragma unroll
    for (int i = 0; i < 8; ++i)
#pragma unroll
        for (int j = 0; j < 4; ++j) acc[i][j] = 0ull;

    const int NKT = DD / 8;
    for (int kt = 0; kt < NKT; ++kt) {
        int buf = kt & 1;
        if (kt < NKT - 1) {
            int k0 = (kt + 1) * 8;
            pa = *(const float4*)(A  + (size_t)(t0 + row) * DD + k0 + c4);
            pb = *(const float4*)(Bm + (size_t)(s0 + row) * DD + k0 + c4);
        }
#pragma unroll
        for (int k = 0; k < 8; ++k)
            mma_step_p(&As2[buf][k][0], &Bs[buf][k][0], ty * 8, tx * 8, acc);
        if (kt < NKT - 1) {
            int nb = buf ^ 1;
            As2[nb][c4 + 0][row] = fdup(pa.x); As2[nb][c4 + 1][row] = fdup(pa.y);
            As2[nb][c4 + 2][row] = fdup(pa.z); As2[nb][c4 + 3][row] = fdup(pa.w);
            Bs[nb][c4 + 0][row] = pb.x; Bs[nb][c4 + 1][row] = pb.y;
            Bs[nb][c4 + 2][row] = pb.z; Bs[nb][c4 + 3][row] = pb.w;
        }
        __syncthreads();
    }

    const int len = decode_len(lens32, bz);

    // unpack + mask + per-thread max over this thread's 8 s-values
    float v[8][8];
#pragma unroll
    for (int i = 0; i < 8; ++i) {
        int sb = s0 + tx * 8;
#pragma unroll
        for (int j = 0; j < 4; ++j) { v[i][2 * j] = lo32(acc[i][j]); v[i][2 * j + 1] = hi32(acc[i][j]); }
        float m = -INFINITY;
#pragma unroll
        for (int jj = 0; jj < 8; ++jj) {
            if (sb + jj >= len) v[i][jj] = -INFINITY;
            m = fmaxf(m, v[i][jj]);
        }
        red[ty * 8 + i][tx] = m;
    }
    __syncthreads();
    // block row max across the 16 tx groups
    if (tid < 128) {
        float m = red[tid][0];
#pragma unroll
        for (int j = 1; j < 16; ++j) m = fmaxf(m, red[tid][j]);
        red[tid][16] = m;
        g_bmax[(bz * TT + t0 + tid) * NSBLK + blockIdx.x] = m;
        atomicMax(&g_rowmax[bz * TT + t0 + tid], fenc(m));
    }
    __syncthreads();

    // e_blk = exp(v - m_blk), store
#pragma unroll
    for (int i = 0; i < 8; ++i) {
        int t = t0 + ty * 8 + i;
        float m = red[ty * 8 + i][16];
        float e[8];
#pragma unroll
        for (int jj = 0; jj < 8; ++jj)
            e[jj] = (v[i][jj] > -INFINITY) ? __expf(v[i][jj] - m) : 0.0f;
        float4* op = (float4*)(g_align + (size_t)(bz * TT + t) * SS + s0 + tx * 8);
        op[0] = make_float4(e[0], e[1], e[2], e[3]);
        op[1] = make_float4(e[4], e[5], e[6], e[7]);
    }
}

// ---------------- Phase A: per-chunk column sums of e_blk * f ----------------
__global__ void __launch_bounds__(256) k_colsum() {
    const int b  = blockIdx.z;
    const int ch = blockIdx.y;
    const int s  = blockIdx.x * 256 + threadIdx.x;
    __shared__ float ffac[TCH][2];
    {
        int tl = threadIdx.x >> 1;          // 0..127
        int sb = threadIdx.x & 1;           // 0..1
        int t  = ch * TCH + tl;
        float mb = g_bmax[(b * TT + t) * NSBLK + blockIdx.x * 2 + sb];
        float mg = fdec(g_rowmax[b * TT + t]);
        ffac[tl][sb] = __expf(mb - mg);
    }
    __syncthreads();
    const int mysb = threadIdx.x >> 7;      // 0..1
    size_t base = (size_t)(b * TT + ch * TCH) * SS + s;
    float sum = 0.f;
#pragma unroll 4
    for (int r = 0; r < TCH; ++r)
        sum += g_align[base + (size_t)r * SS] * ffac[r][mysb];
    g_carry[(b * NCHUNK + ch) * SS + s] = sum;
}

// ---------------- tiny exclusive scan over chunks ----------------
__global__ void k_scan() {
    int i = blockIdx.x * blockDim.x + threadIdx.x;
    if (i >= BB * SS) return;
    int b = i / SS, s = i % SS;
    float run = 0.f;
    for (int c = 0; c < NCHUNK; ++c) {
        int idx = (b * NCHUNK + c) * SS + s;
        float v = g_carry[idx];
        g_carry[idx] = run;
        run += v;
    }
}

// ---------------- Phase C: penalty replay, u in place, partial rowsums ----------------
__global__ void __launch_bounds__(256) k_phasec() {
    const int b  = blockIdx.z;
    const int ch = blockIdx.y;
    const int s  = blockIdx.x * 256 + threadIdx.x;
    const int lane = threadIdx.x & 31;
    const int warp = threadIdx.x >> 5;
    __shared__ float ffac[TCH][2];
    {
        int tl = threadIdx.x >> 1;
        int sb = threadIdx.x & 1;
        int t  = ch * TCH + tl;
        float mb = g_bmax[(b * TT + t) * NSBLK + blockIdx.x * 2 + sb];
        float mg = fdec(g_rowmax[b * TT + t]);
        ffac[tl][sb] = __expf(mb - mg);
    }
    __syncthreads();
    const int mysb = threadIdx.x >> 7;

    float P = g_carry[(b * NCHUNK + ch) * SS + s];
    size_t base = (size_t)(b * TT + ch * TCH) * SS + s;
#pragma unroll 2
    for (int r = 0; r < TCH; ++r) {
        int t = ch * TCH + r;
        size_t off = base + (size_t)r * SS;
        float e = g_align[off] * ffac[r][mysb];
        float pen = (t == 0) ? 1.0f : P;
        float u = e / (pen + 1e-20f);
        P += e;
        g_align[off] = u;          // unnormalized weight, in place
        float w = u;
        w += __shfl_down_sync(0xffffffffu, w, 16);
        w += __shfl_down_sync(0xffffffffu, w, 8);
        w += __shfl_down_sync(0xffffffffu, w, 4);
        w += __shfl_down_sync(0xffffffffu, w, 2);
        w += __shfl_down_sync(0xffffffffu, w, 1);
        if (lane == 0) g_partial[(size_t)(b * TT + t) * 64 + blockIdx.x * 8 + warp] = w;
    }
}

// ---------------- deterministic rowsum reduce -> inverse ----------------
__global__ void k_rowsum() {
    int i = blockIdx.x * blockDim.x + threadIdx.x;
    if (i >= BB * TT) return;
    const float* p = g_partial + (size_t)i * 64;
    float s = 0.f;
#pragma unroll
    for (int j = 0; j < 64; ++j) s += p[j];
    g_invsum[i] = 1.0f / s;
}

// ---------------- write normalized align_vectors to d_out ----------------
__global__ void __launch_bounds__(256) k_norm(float* __restrict__ av) {
    int row = blockIdx.x;
    float inv = g_invsum[row];
    const float4* up = (const float4*)(g_align + (size_t)row * SS);
    float4* op = (float4*)(av + (size_t)row * SS);
    int t = threadIdx.x;
    float4 a = up[t];
    a.x *= inv; a.y *= inv; a.z *= inv; a.w *= inv;
    op[t] = a;
    float4 c = up[t + 256];
    c.x *= inv; c.y *= inv; c.z *= inv; c.w *= inv;
    op[t + 256] = c;
}

// ---------------- GEMM2: c = (u @ memory_bank) * invsum ----------------
__global__ void __launch_bounds__(256) k_gemm2(const float* __restrict__ mb) {
    __shared__ __align__(16) unsigned long long As2[2][8][128];
    __shared__ __align__(16) float              Bs [2][8][132];

    const int tid = threadIdx.x;
    const int tx = tid & 15, ty = tid >> 4;
    const int bz = blockIdx.z;
    const int t0 = blockIdx.y * 128;
    const int n0 = blockIdx.x * 128;

    const float* A  = g_align + (size_t)bz * TT * SS;
    const float* Bm = mb      + (size_t)bz * SS * DD;

    const int row = tid >> 1;            // 0..127 (A fill)
    const int c4  = (tid & 1) * 4;
    const int kk  = tid >> 5;            // 0..7  (B fill)
    const int cc  = (tid & 31) * 4;      // 0..124

    float4 pa = *(const float4*)(A + (size_t)(t0 + row) * SS + c4);
    float4 pb = *(const float4*)(Bm + (size_t)kk * DD + n0 + cc);
    {
        As2[0][c4 + 0][row] = fdup(pa.x); As2[0][c4 + 1][row] = fdup(pa.y);
        As2[0][c4 + 2][row] = fdup(pa.z); As2[0][c4 + 3][row] = fdup(pa.w);
        *(float4*)&Bs[0][kk][cc] = pb;
    }
    __syncthreads();

    unsigned long long acc[8][4];
#pragma unroll
    for (int i = 0; i < 8; ++i)
#pragma unroll
        for (int j = 0; j < 4; ++j) acc[i][j] = 0ull;

    const int NKT = SS / 8;
    for (int kt = 0; kt < NKT; ++kt) {
        int buf = kt & 1;
        if (kt < NKT - 1) {
            int k0 = (kt + 1) * 8;
            pa = *(const float4*)(A + (size_t)(t0 + row) * SS + k0 + c4);
            pb = *(const float4*)(Bm + (size_t)(k0 + kk) * DD + n0 + cc);
        }
#pragma unroll
        for (int k = 0; k < 8; ++k)
            mma_step_p(&As2[buf][k][0], &Bs[buf][k][0], ty * 8, tx * 8, acc);
        if (kt < NKT - 1) {
            int nb = buf ^ 1;
            As2[nb][c4 + 0][row] = fdup(pa.x); As2[nb][c4 + 1][row] = fdup(pa.y);
            As2[nb][c4 + 2][row] = fdup(pa.z); As2[nb][c4 + 3][row] = fdup(pa.w);
            *(float4*)&Bs[nb][kk][cc] = pb;
        }
        __syncthreads();
    }

#pragma unroll
    for (int i = 0; i < 8; ++i) {
        int t = t0 + ty * 8 + i;
        float inv = g_invsum[bz * TT + t];
        float v[8];
#pragma unroll
        for (int j = 0; j < 4; ++j) { v[2 * j] = lo32(acc[i][j]); v[2 * j + 1] = hi32(acc[i][j]); }
#pragma unroll
        for (int jj = 0; jj < 8; ++jj) v[jj] *= inv;
        float4* op = (float4*)(g_c + (size_t)(bz * TT + t) * DD + n0 + tx * 8);
        op[0] = make_float4(v[0], v[1], v[2], v[3]);
        op[1] = make_float4(v[4], v[5], v[6], v[7]);
    }
}

// ---------------- GEMM3: attn_h = tanh([c, source] @ W_out) ----------------
__global__ void __launch_bounds__(256) k_gemm3(const float* __restrict__ src,
                                               const float* __restrict__ W,
                                               float* __restrict__ outh) {
    __shared__ __align__(16) unsigned long long As2[2][8][128];
    __shared__ __align__(16) float              Bs [2][8][132];

    const int tid = threadIdx.x;
    const int tx = tid & 15, ty = tid >> 4;
    const int m0 = blockIdx.y * 128;
    const int n0 = blockIdx.x * 128;

    const int row = tid >> 1;
    const int c4  = (tid & 1) * 4;
    const int kk  = tid >> 5;
    const int cc  = (tid & 31) * 4;

    float4 pa = *(const float4*)(g_c + (size_t)(m0 + row) * DD + c4);
    float4 pb = *(const float4*)(W + (size_t)kk * DD + n0 + cc);
    {
        As2[0][c4 + 0][row] = fdup(pa.x); As2[0][c4 + 1][row] = fdup(pa.y);
        As2[0][c4 + 2][row] = fdup(pa.z); As2[0][c4 + 3][row] = fdup(pa.w);
        *(float4*)&Bs[0][kk][cc] = pb;
    }
    __syncthreads();

    unsigned long long acc[8][4];
#pragma unroll
    for (int i = 0; i < 8; ++i)
#pragma unroll
        for (int j = 0; j < 4; ++j) acc[i][j] = 0ull;

    const int NKT = (2 * DD) / 8;
    for (int kt = 0; kt < NKT; ++kt) {
        int buf = kt & 1;
        if (kt < NKT - 1) {
            int k0 = (kt + 1) * 8;
            int kg = k0 + c4;
            const float* ap = (kg < DD) ? (g_c + (size_t)(m0 + row) * DD + kg)
                                        : (src + (size_t)(m0 + row) * DD + (kg - DD));
            pa = *(const float4*)ap;
            pb = *(const float4*)(W + (size_t)(k0 + kk) * DD + n0 + cc);
        }
#pragma unroll
        for (int k = 0; k < 8; ++k)
            mma_step_p(&As2[buf][k][0], &Bs[buf][k][0], ty * 8, tx * 8, acc);
        if (kt < NKT - 1) {
            int nb = buf ^ 1;
            As2[nb][c4 + 0][row] = fdup(pa.x); As2[nb][c4 + 1][row] = fdup(pa.y);
            As2[nb][c4 + 2][row] = fdup(pa.z); As2[nb][c4 + 3][row] = fdup(pa.w);
            *(float4*)&Bs[nb][kk][cc] = pb;
        }
        __syncthreads();
    }

#pragma unroll
    for (int i = 0; i < 8; ++i) {
        int m = m0 + ty * 8 + i;
        float v[8];
#pragma unroll
        for (int j = 0; j < 4; ++j) { v[2 * j] = lo32(acc[i][j]); v[2 * j + 1] = hi32(acc[i][j]); }
#pragma unroll
        for (int jj = 0; jj < 8; ++jj) v[jj] = tanhf(v[jj]);
        float4* op = (float4*)(outh + (size_t)m * DD + n0 + tx * 8);
        op[0] = make_float4(v[0], v[1], v[2], v[3]);
        op[1] = make_float4(v[4], v[5], v[6], v[7]);
    }
}

// ---------------- launch ----------------
extern "C" void kernel_launch(void* const* d_in, const int* in_sizes, int n_in,
                              void* d_out, int out_size) {
    const float* src  = (const float*)d_in[0];      // [B,T,D]
    const float* mb   = (const float*)d_in[1];      // [B,S,D]
    const float* W    = (const float*)d_in[2];      // [2D,D]
    const int*   lens = (const int*)d_in[3];        // [B] (int32 or int64; decoded in-kernel)

    float* outh = (float*)d_out;                    // attn_h   [B,T,D]
    float* av   = outh + (size_t)BB * TT * DD;      // align_vectors [B,T,S]

    k_init<<<(BB * TT + 255) / 256, 256>>>();
    k_gemm1<<<dim3(SS / 128, TT / 128, BB), 256>>>(src, mb, lens);
    k_colsum<<<dim3(SS / 256, NCHUNK, BB), 256>>>();
    k_scan<<<(BB * SS + 255) / 256, 256>>>();
    k_phasec<<<dim3(SS / 256, NCHUNK, BB), 256>>>();
    k_rowsum<<<(BB * TT + 255) / 256, 256>>>();
    k_norm<<<BB * TT, 256>>>(av);
    k_gemm2<<<dim3(DD / 128, TT / 128, BB), 256>>>(mb);
    k_gemm3<<<dim3(DD / 128, (BB * TT) / 128, 1), 256>>>(src, W, outh);
}

// round 5
// speedup vs baseline: 1.2021x; 1.2021x over previous
#include <cuda_runtime.h>
#include <math.h>
#include <stdint.h>

#define BB 8
#define TT 2048
#define SS 2048
#define DD 256
#define NCHUNK 16
#define TCH 128   /* TT / NCHUNK */
#define NSBLK 16  /* SS / 128 */

// ---------------- scratch (device globals; no runtime allocation) ----------------
__device__ float        g_align [(size_t)BB * TT * SS]; // e_blk, then unnormalized u in place
__device__ float        g_bmax  [BB * TT * NSBLK];      // per (row, s-block) local max
__device__ unsigned int g_rowmax[BB * TT];              // monotone-uint encoded global row max
__device__ float        g_carry [BB * NCHUNK * SS];     // per-chunk column sums -> exclusive prefix
__device__ float        g_partial[(size_t)BB * TT * 64];// per (row, sblk*8+warp) partial rowsums
__device__ float        g_invsum[BB * TT];              // 1 / rowsum
__device__ float        g_c     [(size_t)BB * TT * DD]; // context vectors (16MB)

// ---------------- helpers ----------------
__device__ __forceinline__ void ffma2(unsigned long long& d, unsigned long long a, unsigned long long b) {
    asm("fma.rn.f32x2 %0, %1, %2, %0;" : "+l"(d) : "l"(a), "l"(b));
}
__device__ __forceinline__ unsigned long long fdup(float x) {
    unsigned long long r;
    asm("mov.b64 %0, {%1, %1};" : "=l"(r) : "f"(x));
    return r;
}
__device__ __forceinline__ float lo32(unsigned long long v) { return __uint_as_float((unsigned)(v & 0xffffffffull)); }
__device__ __forceinline__ float hi32(unsigned long long v) { return __uint_as_float((unsigned)(v >> 32)); }

__device__ __forceinline__ unsigned fenc(float f) {
    unsigned u = __float_as_uint(f);
    return (u & 0x80000000u) ? ~u : (u | 0x80000000u);
}
__device__ __forceinline__ float fdec(unsigned e) {
    return (e & 0x80000000u) ? __uint_as_float(e ^ 0x80000000u) : __uint_as_float(~e);
}

// dtype-robust length decode (jax may hand us int32 despite int64 in reference)
__device__ __forceinline__ int decode_len(const int* __restrict__ lens32, int b) {
    bool is64 = (lens32[1] == 0) && (lens32[3] == 0) && (lens32[5] == 0) && (lens32[7] == 0);
    if (is64) return (int)((const long long*)lens32)[b];
    return lens32[b];
}

// shared 8x8 f32x2 outer-product step (round-3 proven version)
__device__ __forceinline__ void mma_step(const float* __restrict__ asrow,
                                         const float* __restrict__ bsrow,
                                         int ty8, int tx8,
                                         unsigned long long acc[8][4]) {
    float4 a0 = *(const float4*)(asrow + ty8);
    float4 a1 = *(const float4*)(asrow + ty8 + 4);
    unsigned long long a[8] = {fdup(a0.x), fdup(a0.y), fdup(a0.z), fdup(a0.w),
                               fdup(a1.x), fdup(a1.y), fdup(a1.z), fdup(a1.w)};
    const unsigned long long* bp = (const unsigned long long*)(bsrow + tx8);
    unsigned long long b0 = bp[0], b1 = bp[1], b2 = bp[2], b3 = bp[3];
#pragma unroll
    for (int i = 0; i < 8; ++i) {
        ffma2(acc[i][0], a[i], b0);
        ffma2(acc[i][1], a[i], b1);
        ffma2(acc[i][2], a[i], b2);
        ffma2(acc[i][3], a[i], b3);
    }
}

// ---------------- init ----------------
__global__ void k_init() {
    int i = blockIdx.x * blockDim.x + threadIdx.x;
    if (i < BB * TT) g_rowmax[i] = 0x007FFFFFu;  // fenc(-inf)
}

// ---------------- GEMM1: logits -> block max -> e_blk = exp(v - m_blk) ----------------
__global__ void __launch_bounds__(256) k_gemm1(const float* __restrict__ src,
                                               const float* __restrict__ mb,
                                               const int* __restrict__ lens32) {
    __shared__ __align__(16) float As[2][16][132];
    __shared__ __align__(16) float Bs[2][16][132];
    __shared__ float red[128][17];

    const int tid = threadIdx.x;
    const int tx = tid & 15, ty = tid >> 4;
    const int bz = blockIdx.z;
    const int t0 = blockIdx.y * 128;
    const int s0 = blockIdx.x * 128;

    const float* A  = src + (size_t)bz * TT * DD;
    const float* Bm = mb  + (size_t)bz * SS * DD;

    const int row0 = tid >> 2;           // 0..63
    const int c4   = (tid & 3) * 4;      // 0,4,8,12

    float4 pa[2], pb[2];
#pragma unroll
    for (int l = 0; l < 2; ++l) {
        int row = row0 + l * 64;
        pa[l] = *(const float4*)(A  + (size_t)(t0 + row) * DD + c4);
        pb[l] = *(const float4*)(Bm + (size_t)(s0 + row) * DD + c4);
    }
#pragma unroll
    for (int l = 0; l < 2; ++l) {
        int row = row0 + l * 64;
        As[0][c4 + 0][row] = pa[l].x; As[0][c4 + 1][row] = pa[l].y;
        As[0][c4 + 2][row] = pa[l].z; As[0][c4 + 3][row] = pa[l].w;
        Bs[0][c4 + 0][row] = pb[l].x; Bs[0][c4 + 1][row] = pb[l].y;
        Bs[0][c4 + 2][row] = pb[l].z; Bs[0][c4 + 3][row] = pb[l].w;
    }
    __syncthreads();

    unsigned long long acc[8][4];
#pragma unroll
    for (int i = 0; i < 8; ++i)
#pragma unroll
        for (int j = 0; j < 4; ++j) acc[i][j] = 0ull;

    for (int kt = 0; kt < 16; ++kt) {
        int buf = kt & 1;
        if (kt < 15) {
            int k0 = (kt + 1) * 16;
#pragma unroll
            for (int l = 0; l < 2; ++l) {
                int row = row0 + l * 64;
                pa[l] = *(const float4*)(A  + (size_t)(t0 + row) * DD + k0 + c4);
                pb[l] = *(const float4*)(Bm + (size_t)(s0 + row) * DD + k0 + c4);
            }
        }
#pragma unroll
        for (int k = 0; k < 16; ++k)
            mma_step(&As[buf][k][0], &Bs[buf][k][0], ty * 8, tx * 8, acc);
        if (kt < 15) {
            int nb = buf ^ 1;
#pragma unroll
            for (int l = 0; l < 2; ++l) {
                int row = row0 + l * 64;
                As[nb][c4 + 0][row] = pa[l].x; As[nb][c4 + 1][row] = pa[l].y;
                As[nb][c4 + 2][row] = pa[l].z; As[nb][c4 + 3][row] = pa[l].w;
                Bs[nb][c4 + 0][row] = pb[l].x; Bs[nb][c4 + 1][row] = pb[l].y;
                Bs[nb][c4 + 2][row] = pb[l].z; Bs[nb][c4 + 3][row] = pb[l].w;
            }
        }
        __syncthreads();
    }

    const int len = decode_len(lens32, bz);
    const int sb = s0 + tx * 8;
    // nvalid: how many of this thread's 8 s-positions are in range
    int nvalid = len - sb; nvalid = nvalid < 0 ? 0 : (nvalid > 8 ? 8 : nvalid);

    // pass 1: per-thread masked max straight from acc (no extra live array)
#pragma unroll
    for (int i = 0; i < 8; ++i) {
        float m = -INFINITY;
#pragma unroll
        for (int j = 0; j < 4; ++j) {
            float x0 = lo32(acc[i][j]), x1 = hi32(acc[i][j]);
            if (2 * j + 0 < nvalid) m = fmaxf(m, x0);
            if (2 * j + 1 < nvalid) m = fmaxf(m, x1);
        }
        red[ty * 8 + i][tx] = m;
    }
    __syncthreads();
    if (tid < 128) {
        float m = red[tid][0];
#pragma unroll
        for (int j = 1; j < 16; ++j) m = fmaxf(m, red[tid][j]);
        red[tid][16] = m;
        g_bmax[(bz * TT + t0 + tid) * NSBLK + blockIdx.x] = m;
        atomicMax(&g_rowmax[bz * TT + t0 + tid], fenc(m));
    }
    __syncthreads();

    // pass 2: recompute masked value from acc, exp, store
#pragma unroll
    for (int i = 0; i < 8; ++i) {
        int t = t0 + ty * 8 + i;
        float m = red[ty * 8 + i][16];
        float e[8];
#pragma unroll
        for (int j = 0; j < 4; ++j) {
            float x0 = lo32(acc[i][j]), x1 = hi32(acc[i][j]);
            e[2 * j + 0] = (2 * j + 0 < nvalid) ? __expf(x0 - m) : 0.0f;
            e[2 * j + 1] = (2 * j + 1 < nvalid) ? __expf(x1 - m) : 0.0f;
        }
        float4* op = (float4*)(g_align + (size_t)(bz * TT + t) * SS + sb);
        op[0] = make_float4(e[0], e[1], e[2], e[3]);
        op[1] = make_float4(e[4], e[5], e[6], e[7]);
    }
}

// ---------------- Phase A: per-chunk column sums of e_blk * f ----------------
__global__ void __launch_bounds__(256) k_colsum() {
    const int b  = blockIdx.z;
    const int ch = blockIdx.y;
    const int s  = blockIdx.x * 256 + threadIdx.x;
    __shared__ float ffac[TCH][2];
    {
        int tl = threadIdx.x >> 1;          // 0..127
        int sb = threadIdx.x & 1;           // 0..1
        int t  = ch * TCH + tl;
        float mb = g_bmax[(b * TT + t) * NSBLK + blockIdx.x * 2 + sb];
        float mg = fdec(g_rowmax[b * TT + t]);
        ffac[tl][sb] = __expf(mb - mg);
    }
    __syncthreads();
    const int mysb = threadIdx.x >> 7;      // 0..1
    size_t base = (size_t)(b * TT + ch * TCH) * SS + s;
    float sum = 0.f;
#pragma unroll 4
    for (int r = 0; r < TCH; ++r)
        sum += g_align[base + (size_t)r * SS] * ffac[r][mysb];
    g_carry[(b * NCHUNK + ch) * SS + s] = sum;
}

// ---------------- tiny exclusive scan over chunks ----------------
__global__ void k_scan() {
    int i = blockIdx.x * blockDim.x + threadIdx.x;
    if (i >= BB * SS) return;
    int b = i / SS, s = i % SS;
    float run = 0.f;
    for (int c = 0; c < NCHUNK; ++c) {
        int idx = (b * NCHUNK + c) * SS + s;
        float v = g_carry[idx];
        g_carry[idx] = run;
        run += v;
    }
}

// ---------------- Phase C: penalty replay, u in place, partial rowsums ----------------
__global__ void __launch_bounds__(256) k_phasec() {
    const int b  = blockIdx.z;
    const int ch = blockIdx.y;
    const int s  = blockIdx.x * 256 + threadIdx.x;
    const int lane = threadIdx.x & 31;
    const int warp = threadIdx.x >> 5;
    __shared__ float ffac[TCH][2];
    {
        int tl = threadIdx.x >> 1;
        int sb = threadIdx.x & 1;
        int t  = ch * TCH + tl;
        float mb = g_bmax[(b * TT + t) * NSBLK + blockIdx.x * 2 + sb];
        float mg = fdec(g_rowmax[b * TT + t]);
        ffac[tl][sb] = __expf(mb - mg);
    }
    __syncthreads();
    const int mysb = threadIdx.x >> 7;

    float P = g_carry[(b * NCHUNK + ch) * SS + s];
    size_t base = (size_t)(b * TT + ch * TCH) * SS + s;
#pragma unroll 2
    for (int r = 0; r < TCH; ++r) {
        int t = ch * TCH + r;
        size_t off = base + (size_t)r * SS;
        float e = g_align[off] * ffac[r][mysb];
        float pen = (t == 0) ? 1.0f : P;
        float u = e / (pen + 1e-20f);
        P += e;
        g_align[off] = u;          // unnormalized weight, in place
        float w = u;
        w += __shfl_down_sync(0xffffffffu, w, 16);
        w += __shfl_down_sync(0xffffffffu, w, 8);
        w += __shfl_down_sync(0xffffffffu, w, 4);
        w += __shfl_down_sync(0xffffffffu, w, 2);
        w += __shfl_down_sync(0xffffffffu, w, 1);
        if (lane == 0) g_partial[(size_t)(b * TT + t) * 64 + blockIdx.x * 8 + warp] = w;
    }
}

// ---------------- deterministic rowsum reduce -> inverse ----------------
__global__ void k_rowsum() {
    int i = blockIdx.x * blockDim.x + threadIdx.x;
    if (i >= BB * TT) return;
    const float* p = g_partial + (size_t)i * 64;
    float s = 0.f;
#pragma unroll
    for (int j = 0; j < 64; ++j) s += p[j];
    g_invsum[i] = 1.0f / s;
}

// ---------------- write normalized align_vectors to d_out ----------------
__global__ void __launch_bounds__(256) k_norm(float* __restrict__ av) {
    int row = blockIdx.x;
    float inv = g_invsum[row];
    const float4* up = (const float4*)(g_align + (size_t)row * SS);
    float4* op = (float4*)(av + (size_t)row * SS);
    int t = threadIdx.x;
    float4 a = up[t];
    a.x *= inv; a.y *= inv; a.z *= inv; a.w *= inv;
    op[t] = a;
    float4 c = up[t + 256];
    c.x *= inv; c.y *= inv; c.z *= inv; c.w *= inv;
    op[t + 256] = c;
}

// ---------------- GEMM2: c = (u @ memory_bank) * invsum ----------------
__global__ void __launch_bounds__(256) k_gemm2(const float* __restrict__ mb) {
    __shared__ __align__(16) float As[2][16][132];
    __shared__ __align__(16) float Bs[2][16][132];

    const int tid = threadIdx.x;
    const int tx = tid & 15, ty = tid >> 4;
    const int bz = blockIdx.z;
    const int t0 = blockIdx.y * 128;
    const int n0 = blockIdx.x * 128;

    const float* A  = g_align + (size_t)bz * TT * SS;
    const float* Bm = mb      + (size_t)bz * SS * DD;

    const int row0 = tid >> 2;
    const int c4   = (tid & 3) * 4;
    const int r2_0 = tid >> 5;           // 0..7
    const int c2   = (tid & 31) * 4;     // 0..124

    float4 pa[2], pb[2];
#pragma unroll
    for (int l = 0; l < 2; ++l) {
        int row = row0 + l * 64;
        pa[l] = *(const float4*)(A + (size_t)(t0 + row) * SS + c4);
        int r2 = r2_0 + l * 8;
        pb[l] = *(const float4*)(Bm + (size_t)r2 * DD + n0 + c2);
    }
#pragma unroll
    for (int l = 0; l < 2; ++l) {
        int row = row0 + l * 64;
        As[0][c4 + 0][row] = pa[l].x; As[0][c4 + 1][row] = pa[l].y;
        As[0][c4 + 2][row] = pa[l].z; As[0][c4 + 3][row] = pa[l].w;
        int r2 = r2_0 + l * 8;
        *(float4*)&Bs[0][r2][c2] = pb[l];
    }
    __syncthreads();

    unsigned long long acc[8][4];
#pragma unroll
    for (int i = 0; i < 8; ++i)
#pragma unroll
        for (int j = 0; j < 4; ++j) acc[i][j] = 0ull;

    for (int kt = 0; kt < SS / 16; ++kt) {
        int buf = kt & 1;
        if (kt < SS / 16 - 1) {
            int k0 = (kt + 1) * 16;
#pragma unroll
            for (int l = 0; l < 2; ++l) {
                int row = row0 + l * 64;
                pa[l] = *(const float4*)(A + (size_t)(t0 + row) * SS + k0 + c4);
                int r2 = r2_0 + l * 8;
                pb[l] = *(const float4*)(Bm + (size_t)(k0 + r2) * DD + n0 + c2);
            }
        }
#pragma unroll
        for (int k = 0; k < 16; ++k)
            mma_step(&As[buf][k][0], &Bs[buf][k][0], ty * 8, tx * 8, acc);
        if (kt < SS / 16 - 1) {
            int nb = buf ^ 1;
#pragma unroll
            for (int l = 0; l < 2; ++l) {
                int row = row0 + l * 64;
                As[nb][c4 + 0][row] = pa[l].x; As[nb][c4 + 1][row] = pa[l].y;
                As[nb][c4 + 2][row] = pa[l].z; As[nb][c4 + 3][row] = pa[l].w;
                int r2 = r2_0 + l * 8;
                *(float4*)&Bs[nb][r2][c2] = pb[l];
            }
        }
        __syncthreads();
    }

#pragma unroll
    for (int i = 0; i < 8; ++i) {
        int t = t0 + ty * 8 + i;
        float inv = g_invsum[bz * TT + t];
        float v[8];
#pragma unroll
        for (int j = 0; j < 4; ++j) { v[2 * j] = lo32(acc[i][j]); v[2 * j + 1] = hi32(acc[i][j]); }
#pragma unroll
        for (int jj = 0; jj < 8; ++jj) v[jj] *= inv;
        float4* op = (float4*)(g_c + (size_t)(bz * TT + t) * DD + n0 + tx * 8);
        op[0] = make_float4(v[0], v[1], v[2], v[3]);
        op[1] = make_float4(v[4], v[5], v[6], v[7]);
    }
}

// ---------------- GEMM3: attn_h = tanh([c, source] @ W_out) ----------------
__global__ void __launch_bounds__(256) k_gemm3(const float* __restrict__ src,
                                               const float* __restrict__ W,
                                               float* __restrict__ outh) {
    __shared__ __align__(16) float As[2][16][132];
    __shared__ __align__(16) float Bs[2][16][132];

    const int tid = threadIdx.x;
    const int tx = tid & 15, ty = tid >> 4;
    const int m0 = blockIdx.y * 128;
    const int n0 = blockIdx.x * 128;

    const int row0 = tid >> 2;
    const int c4   = (tid & 3) * 4;
    const int r2_0 = tid >> 5;
    const int c2   = (tid & 31) * 4;

    float4 pa[2], pb[2];
#pragma unroll
    for (int l = 0; l < 2; ++l) {
        int row = row0 + l * 64;
        int m = m0 + row;
        pa[l] = *(const float4*)(g_c + (size_t)m * DD + c4);
        int r2 = r2_0 + l * 8;
        pb[l] = *(const float4*)(W + (size_t)r2 * DD + n0 + c2);
    }
#pragma unroll
    for (int l = 0; l < 2; ++l) {
        int row = row0 + l * 64;
        As[0][c4 + 0][row] = pa[l].x; As[0][c4 + 1][row] = pa[l].y;
        As[0][c4 + 2][row] = pa[l].z; As[0][c4 + 3][row] = pa[l].w;
        int r2 = r2_0 + l * 8;
        *(float4*)&Bs[0][r2][c2] = pb[l];
    }
    __syncthreads();

    unsigned long long acc[8][4];
#pragma unroll
    for (int i = 0; i < 8; ++i)
#pragma unroll
        for (int j = 0; j < 4; ++j) acc[i][j] = 0ull;

    for (int kt = 0; kt < (2 * DD) / 16; ++kt) {
        int buf = kt & 1;
        if (kt < (2 * DD) / 16 - 1) {
            int k0 = (kt + 1) * 16;
#pragma unroll
            for (int l = 0; l < 2; ++l) {
                int row = row0 + l * 64;
                int m = m0 + row;
                int kg = k0 + c4;
                const float* ap = (kg < DD) ? (g_c + (size_t)m * DD + kg)
                                            : (src + (size_t)m * DD + (kg - DD));
                pa[l] = *(const float4*)ap;
                int r2 = r2_0 + l * 8;
                pb[l] = *(const float4*)(W + (size_t)(k0 + r2) * DD + n0 + c2);
            }
        }
#pragma unroll
        for (int k = 0; k < 16; ++k)
            mma_step(&As[buf][k][0], &Bs[buf][k][0], ty * 8, tx * 8, acc);
        if (kt < (2 * DD) / 16 - 1) {
            int nb = buf ^ 1;
#pragma unroll
            for (int l = 0; l < 2; ++l) {
                int row = row0 + l * 64;
                As[nb][c4 + 0][row] = pa[l].x; As[nb][c4 + 1][row] = pa[l].y;
                As[nb][c4 + 2][row] = pa[l].z; As[nb][c4 + 3][row] = pa[l].w;
                int r2 = r2_0 + l * 8;
                *(float4*)&Bs[nb][r2][c2] = pb[l];
            }
        }
        __syncthreads();
    }

#pragma unroll
    for (int i = 0; i < 8; ++i) {
        int m = m0 + ty * 8 + i;
        float v[8];
#pragma unroll
        for (int j = 0; j < 4; ++j) { v[2 * j] = lo32(acc[i][j]); v[2 * j + 1] = hi32(acc[i][j]); }
#pragma unroll
        for (int jj = 0; jj < 8; ++jj) v[jj] = tanhf(v[jj]);
        float4* op = (float4*)(outh + (size_t)m * DD + n0 + tx * 8);
        op[0] = make_float4(v[0], v[1], v[2], v[3]);
        op[1] = make_float4(v[4], v[5], v[6], v[7]);
    }
}

// ---------------- launch ----------------
extern "C" void kernel_launch(void* const* d_in, const int* in_sizes, int n_in,
                              void* d_out, int out_size) {
    const float* src  = (const float*)d_in[0];      // [B,T,D]
    const float* mb   = (const float*)d_in[1];      // [B,S,D]
    const float* W    = (const float*)d_in[2];      // [2D,D]
    const int*   lens = (const int*)d_in[3];        // [B] (int32 or int64; decoded in-kernel)

    float* outh = (float*)d_out;                    // attn_h   [B,T,D]
    float* av   = outh + (size_t)BB * TT * DD;      // align_vectors [B,T,S]

    k_init<<<(BB * TT + 255) / 256, 256>>>();
    k_gemm1<<<dim3(SS / 128, TT / 128, BB), 256>>>(src, mb, lens);
    k_colsum<<<dim3(SS / 256, NCHUNK, BB), 256>>>();
    k_scan<<<(BB * SS + 255) / 256, 256>>>();
    k_phasec<<<dim3(SS / 256, NCHUNK, BB), 256>>>();
    k_rowsum<<<(BB * TT + 255) / 256, 256>>>();
    k_norm<<<BB * TT, 256>>>(av);
    k_gemm2<<<dim3(DD / 128, TT / 128, BB), 256>>>(mb);
    k_gemm3<<<dim3(DD / 128, (BB * TT) / 128, 1), 256>>>(src, W, outh);
}

// round 7
// speedup vs baseline: 1.3033x; 1.0842x over previous
#include <cuda_runtime.h>
#include <math.h>
#include <stdint.h>

#define BB 8
#define TT 2048
#define SS 2048
#define DD 256
#define NCHUNK 16
#define TCH 128   /* TT / NCHUNK */
#define NSBLK 16  /* SS / 128 */

#define CH_K 32
#define A_PITCH 36
#define TILE_SMEM (128 * A_PITCH * 4)   /* 18432 B */
#define BUF_SZ (4 * TILE_SMEM)          /* 73728 B */
#define GSM_TOTAL (2 * BUF_SZ)          /* 147456 B */

// ---------------- scratch (device globals; no runtime allocation) ----------------
__device__ float        g_align [(size_t)BB * TT * SS]; // e_blk, then u_hi in place
__device__ float        g_ulo   [(size_t)BB * TT * SS]; // u_lo (tf32)
__device__ float        g_bmax  [(size_t)BB * TT * NSBLK];
__device__ unsigned int g_rowmax[BB * TT];
__device__ float        g_carry [BB * NCHUNK * SS];
__device__ float        g_partial[(size_t)BB * TT * 64];
__device__ float        g_invsum[BB * TT];
__device__ float        g_c     [(size_t)BB * TT * DD];
__device__ float        g_srchi [(size_t)BB * TT * DD];
__device__ float        g_srclo [(size_t)BB * TT * DD];
__device__ float        g_mbhi  [(size_t)BB * SS * DD];
__device__ float        g_mblo  [(size_t)BB * SS * DD];
__device__ float        g_mbthi [(size_t)BB * DD * SS]; // transposed [B,D,S]
__device__ float        g_mbtlo [(size_t)BB * DD * SS];

// ---------------- generic helpers ----------------
__device__ __forceinline__ void ffma2(unsigned long long& d, unsigned long long a, unsigned long long b) {
    asm("fma.rn.f32x2 %0, %1, %2, %0;" : "+l"(d) : "l"(a), "l"(b));
}
__device__ __forceinline__ unsigned long long fdup(float x) {
    unsigned long long r;
    asm("mov.b64 %0, {%1, %1};" : "=l"(r) : "f"(x));
    return r;
}
__device__ __forceinline__ float lo32(unsigned long long v) { return __uint_as_float((unsigned)(v & 0xffffffffull)); }
__device__ __forceinline__ float hi32(unsigned long long v) { return __uint_as_float((unsigned)(v >> 32)); }
__device__ __forceinline__ unsigned fenc(float f) {
    unsigned u = __float_as_uint(f);
    return (u & 0x80000000u) ? ~u : (u | 0x80000000u);
}
__device__ __forceinline__ float fdec(unsigned e) {
    return (e & 0x80000000u) ? __uint_as_float(e ^ 0x80000000u) : __uint_as_float(~e);
}
__device__ __forceinline__ int decode_len(const int* __restrict__ lens32, int b) {
    bool is64 = (lens32[1] == 0) && (lens32[3] == 0) && (lens32[5] == 0) && (lens32[7] == 0);
    if (is64) return (int)((const long long*)lens32)[b];
    return lens32[b];
}
__device__ __forceinline__ float tf32_rna(float x) {
    unsigned r;
    asm("cvt.rna.tf32.f32 %0, %1;" : "=r"(r) : "f"(x));
    return __uint_as_float(r);
}
__device__ __forceinline__ uint32_t smem_u32(const void* p) {
    uint32_t a;
    asm("{ .reg .u64 t; cvta.to.shared.u64 t, %1; cvt.u32.u64 %0, t; }" : "=r"(a) : "l"(p));
    return a;
}

// ---------------- cp.async + mma.sync infra (plain sm_80+ PTX, no 'a' features) ----
__device__ __forceinline__ void cp16(uint32_t dst, const void* src) {
    asm volatile("cp.async.cg.shared.global [%0], [%1], 16;" :: "r"(dst), "l"(src));
}
__device__ __forceinline__ void cp_commit() { asm volatile("cp.async.commit_group;" ::: "memory"); }
__device__ __forceinline__ void cp_wait0()  { asm volatile("cp.async.wait_group 0;" ::: "memory"); }

__device__ __forceinline__ void ld_chunk(uint32_t smbase, const float* src, size_t stride, int tid) {
    int r0 = tid >> 3, c = tid & 7;
#pragma unroll
    for (int p = 0; p < 4; ++p) {
        int row = r0 + p * 32;
        cp16(smbase + row * (A_PITCH * 4) + c * 16, src + (size_t)row * stride + c * 4);
    }
}

__device__ __forceinline__ void mma_tf32(float* d, uint32_t a0, uint32_t a1, uint32_t a2, uint32_t a3,
                                         uint32_t b0, uint32_t b1) {
    asm volatile("mma.sync.aligned.m16n8k8.row.col.f32.tf32.tf32.f32 "
                 "{%0,%1,%2,%3}, {%4,%5,%6,%7}, {%8,%9}, {%0,%1,%2,%3};"
                 : "+f"(d[0]), "+f"(d[1]), "+f"(d[2]), "+f"(d[3])
                 : "r"(a0), "r"(a1), "r"(a2), "r"(a3), "r"(b0), "r"(b1));
}

// mainloop: acc[128x128 CTA tile] = 3xTF32( A[128 x K], B[128 x K] ), cp.async double-buffered
__device__ __forceinline__ void tc_loop(char* smem,
        const float* __restrict__ Ah, const float* __restrict__ Al, size_t sA,
        const float* __restrict__ Bh, const float* __restrict__ Bl, size_t sB,
        int nck, float acc[4][4][4]) {
    const int tid = threadIdx.x;
    const int lane = tid & 31, wid = tid >> 5;
    const int wm = wid >> 2, wn = wid & 3;
    const int g = lane >> 2, tg = lane & 3;
    uint32_t sb = smem_u32(smem);

#pragma unroll
    for (int i = 0; i < 4; ++i)
#pragma unroll
        for (int j = 0; j < 4; ++j)
#pragma unroll
            for (int q = 0; q < 4; ++q) acc[i][j][q] = 0.f;

    ld_chunk(sb + 0 * TILE_SMEM, Ah, sA, tid);
    ld_chunk(sb + 1 * TILE_SMEM, Al, sA, tid);
    ld_chunk(sb + 2 * TILE_SMEM, Bh, sB, tid);
    ld_chunk(sb + 3 * TILE_SMEM, Bl, sB, tid);
    cp_commit();

    int buf = 0;
    for (int ck = 0; ck < nck; ++ck) {
        cp_wait0();
        __syncthreads();
        if (ck + 1 < nck) {
            uint32_t nb = sb + (buf ^ 1) * BUF_SZ;
            size_t ko = (size_t)(ck + 1) * CH_K;
            ld_chunk(nb + 0 * TILE_SMEM, Ah + ko, sA, tid);
            ld_chunk(nb + 1 * TILE_SMEM, Al + ko, sA, tid);
            ld_chunk(nb + 2 * TILE_SMEM, Bh + ko, sB, tid);
            ld_chunk(nb + 3 * TILE_SMEM, Bl + ko, sB, tid);
            cp_commit();
        }
        const float* Ash = (const float*)(smem + buf * BUF_SZ);
        const float* Asl = Ash + 128 * A_PITCH;
        const float* Bsh = Asl + 128 * A_PITCH;
        const float* Bsl = Bsh + 128 * A_PITCH;
#pragma unroll
        for (int ks = 0; ks < 4; ++ks) {
            int k0 = ks * 8;
            uint32_t bh[4][2], bl[4][2];
#pragma unroll
            for (int nt = 0; nt < 4; ++nt) {
                int o = (wn * 32 + nt * 8 + g) * A_PITCH + k0 + tg;
                bh[nt][0] = __float_as_uint(Bsh[o]);
                bh[nt][1] = __float_as_uint(Bsh[o + 4]);
                bl[nt][0] = __float_as_uint(Bsl[o]);
                bl[nt][1] = __float_as_uint(Bsl[o + 4]);
            }
#pragma unroll
            for (int mt = 0; mt < 4; ++mt) {
                int o = (wm * 64 + mt * 16 + g) * A_PITCH + k0 + tg;
                uint32_t ah0 = __float_as_uint(Ash[o]);
                uint32_t ah1 = __float_as_uint(Ash[o + 8 * A_PITCH]);
                uint32_t ah2 = __float_as_uint(Ash[o + 4]);
                uint32_t ah3 = __float_as_uint(Ash[o + 8 * A_PITCH + 4]);
                uint32_t al0 = __float_as_uint(Asl[o]);
                uint32_t al1 = __float_as_uint(Asl[o + 8 * A_PITCH]);
                uint32_t al2 = __float_as_uint(Asl[o + 4]);
                uint32_t al3 = __float_as_uint(Asl[o + 8 * A_PITCH + 4]);
#pragma unroll
                for (int nt = 0; nt < 4; ++nt) {
                    mma_tf32(acc[mt][nt], ah0, ah1, ah2, ah3, bl[nt][0], bl[nt][1]);
                    mma_tf32(acc[mt][nt], al0, al1, al2, al3, bh[nt][0], bh[nt][1]);
                    mma_tf32(acc[mt][nt], ah0, ah1, ah2, ah3, bh[nt][0], bh[nt][1]);
                }
            }
        }
        buf ^= 1;
    }
}

// ---------------- init ----------------
__global__ void k_init() {
    int i = blockIdx.x * blockDim.x + threadIdx.x;
    if (i < BB * TT) g_rowmax[i] = 0x007FFFFFu;  // fenc(-inf)
}

// ---------------- split fp32 -> (tf32 hi, tf32 lo) elementwise ----------------
__global__ void k_split(const float4* __restrict__ x, float4* __restrict__ hi,
                        float4* __restrict__ lo, int n4) {
    int i = blockIdx.x * 256 + threadIdx.x;
    if (i >= n4) return;
    float4 v = x[i], h, l;
    h.x = tf32_rna(v.x); l.x = tf32_rna(v.x - h.x);
    h.y = tf32_rna(v.y); l.y = tf32_rna(v.y - h.y);
    h.z = tf32_rna(v.z); l.z = tf32_rna(v.z - h.z);
    h.w = tf32_rna(v.w); l.w = tf32_rna(v.w - h.w);
    hi[i] = h; lo[i] = l;
}

// ---------------- transpose + split: mb[B,S,D] -> mbT hi/lo [B,D,S] ----------------
__global__ void k_tsplit(const float* __restrict__ mb) {
    __shared__ float tile[32][33];
    int tx = threadIdx.x & 31, ty = threadIdx.x >> 5;
    int s0 = blockIdx.x * 32, d0 = blockIdx.y * 32, b = blockIdx.z;
#pragma unroll
    for (int j = 0; j < 4; ++j)
        tile[ty + j * 8][tx] = mb[((size_t)b * SS + s0 + ty + j * 8) * DD + d0 + tx];
    __syncthreads();
#pragma unroll
    for (int j = 0; j < 4; ++j) {
        float x = tile[tx][ty + j * 8];
        float h = tf32_rna(x);
        size_t o = ((size_t)b * DD + d0 + ty + j * 8) * SS + s0 + tx;
        g_mbthi[o] = h;
        g_mbtlo[o] = tf32_rna(x - h);
    }
}

// ---------------- GEMM1 (mma.sync tf32): logits -> mask -> block max -> e_blk ----------------
__global__ void __launch_bounds__(256) k_gemm1_mma(const int* __restrict__ lens32) {
    extern __shared__ char smem[];
    const int bz = blockIdx.z, t0 = blockIdx.y * 128, s0 = blockIdx.x * 128;

    float acc[4][4][4];
    tc_loop(smem,
            g_srchi + (size_t)(bz * TT + t0) * DD, g_srclo + (size_t)(bz * TT + t0) * DD, DD,
            g_mbhi + (size_t)(bz * SS + s0) * DD, g_mblo + (size_t)(bz * SS + s0) * DD, DD,
            DD / CH_K, acc);
    __syncthreads();

    const int tid = threadIdx.x, lane = tid & 31, wid = tid >> 5;
    const int wm = wid >> 2, wn = wid & 3, g = lane >> 2, tg = lane & 3;
    const int len = decode_len(lens32, bz);
    float (*red)[17] = (float(*)[17])smem;

#pragma unroll
    for (int mt = 0; mt < 4; ++mt) {
#pragma unroll
        for (int h = 0; h < 2; ++h) {
            int row = wm * 64 + mt * 16 + h * 8 + g;
            float m = -INFINITY;
#pragma unroll
            for (int nt = 0; nt < 4; ++nt) {
                int sg = s0 + wn * 32 + nt * 8 + tg * 2;
                if (sg < len)     m = fmaxf(m, acc[mt][nt][h * 2 + 0]);
                if (sg + 1 < len) m = fmaxf(m, acc[mt][nt][h * 2 + 1]);
            }
            red[row][wn * 4 + tg] = m;
        }
    }
    __syncthreads();
    if (tid < 128) {
        float m = red[tid][0];
#pragma unroll
        for (int j = 1; j < 16; ++j) m = fmaxf(m, red[tid][j]);
        red[tid][16] = m;
        g_bmax[(size_t)(bz * TT + t0 + tid) * NSBLK + blockIdx.x] = m;
        atomicMax(&g_rowmax[bz * TT + t0 + tid], fenc(m));
    }
    __syncthreads();

#pragma unroll
    for (int mt = 0; mt < 4; ++mt) {
#pragma unroll
        for (int h = 0; h < 2; ++h) {
            int row = wm * 64 + mt * 16 + h * 8 + g;
            float m = red[row][16];
            float* orow = g_align + (size_t)(bz * TT + t0 + row) * SS + s0;
#pragma unroll
            for (int nt = 0; nt < 4; ++nt) {
                int col = wn * 32 + nt * 8 + tg * 2;
                int sg = s0 + col;
                float e0 = (sg < len)     ? __expf(acc[mt][nt][h * 2 + 0] - m) : 0.f;
                float e1 = (sg + 1 < len) ? __expf(acc[mt][nt][h * 2 + 1] - m) : 0.f;
                *(float2*)(orow + col) = make_float2(e0, e1);
            }
        }
    }
}

// ---------------- Phase A: per-chunk column sums of e_blk * f ----------------
__global__ void __launch_bounds__(256) k_colsum() {
    const int b  = blockIdx.z;
    const int ch = blockIdx.y;
    const int s  = blockIdx.x * 256 + threadIdx.x;
    __shared__ float ffac[TCH][2];
    {
        int tl = threadIdx.x >> 1;
        int sb = threadIdx.x & 1;
        int t  = ch * TCH + tl;
        float mb_ = g_bmax[(size_t)(b * TT + t) * NSBLK + blockIdx.x * 2 + sb];
        float mg  = fdec(g_rowmax[b * TT + t]);
        ffac[tl][sb] = __expf(mb_ - mg);
    }
    __syncthreads();
    const int mysb = threadIdx.x >> 7;
    size_t base = (size_t)(b * TT + ch * TCH) * SS + s;
    float sum = 0.f;
#pragma unroll 4
    for (int r = 0; r < TCH; ++r)
        sum += g_align[base + (size_t)r * SS] * ffac[r][mysb];
    g_carry[(b * NCHUNK + ch) * SS + s] = sum;
}

// ---------------- tiny exclusive scan over chunks ----------------
__global__ void k_scan() {
    int i = blockIdx.x * blockDim.x + threadIdx.x;
    if (i >= BB * SS) return;
    int b = i / SS, s = i % SS;
    float run = 0.f;
    for (int c = 0; c < NCHUNK; ++c) {
        int idx = (b * NCHUNK + c) * SS + s;
        float v = g_carry[idx];
        g_carry[idx] = run;
        run += v;
    }
}

// ---------------- Phase C: penalty replay, u split hi/lo, partial rowsums ----------------
__global__ void __launch_bounds__(256) k_phasec() {
    const int b  = blockIdx.z;
    const int ch = blockIdx.y;
    const int s  = blockIdx.x * 256 + threadIdx.x;
    const int lane = threadIdx.x & 31;
    const int warp = threadIdx.x >> 5;
    __shared__ float ffac[TCH][2];
    {
        int tl = threadIdx.x >> 1;
        int sb = threadIdx.x & 1;
        int t  = ch * TCH + tl;
        float mb_ = g_bmax[(size_t)(b * TT + t) * NSBLK + blockIdx.x * 2 + sb];
        float mg  = fdec(g_rowmax[b * TT + t]);
        ffac[tl][sb] = __expf(mb_ - mg);
    }
    __syncthreads();
    const int mysb = threadIdx.x >> 7;

    float P = g_carry[(b * NCHUNK + ch) * SS + s];
    size_t base = (size_t)(b * TT + ch * TCH) * SS + s;
#pragma unroll 2
    for (int r = 0; r < TCH; ++r) {
        int t = ch * TCH + r;
        size_t off = base + (size_t)r * SS;
        float e = g_align[off] * ffac[r][mysb];
        float pen = (t == 0) ? 1.0f : P;
        float u = e / (pen + 1e-20f);
        P += e;
        float uh = tf32_rna(u);
        g_align[off] = uh;
        g_ulo[off]   = tf32_rna(u - uh);
        float w = u;
        w += __shfl_down_sync(0xffffffffu, w, 16);
        w += __shfl_down_sync(0xffffffffu, w, 8);
        w += __shfl_down_sync(0xffffffffu, w, 4);
        w += __shfl_down_sync(0xffffffffu, w, 2);
        w += __shfl_down_sync(0xffffffffu, w, 1);
        if (lane == 0) g_partial[(size_t)(b * TT + t) * 64 + blockIdx.x * 8 + warp] = w;
    }
}

// ---------------- deterministic rowsum reduce -> inverse ----------------
__global__ void k_rowsum() {
    int i = blockIdx.x * blockDim.x + threadIdx.x;
    if (i >= BB * TT) return;
    const float* p = g_partial + (size_t)i * 64;
    float s = 0.f;
#pragma unroll
    for (int j = 0; j < 64; ++j) s += p[j];
    g_invsum[i] = 1.0f / s;
}

// ---------------- write normalized align_vectors to d_out (u = hi + lo) ----------------
__global__ void __launch_bounds__(256) k_norm(float* __restrict__ av) {
    int row = blockIdx.x;
    float inv = g_invsum[row];
    const float4* hp = (const float4*)(g_align + (size_t)row * SS);
    const float4* lp = (const float4*)(g_ulo   + (size_t)row * SS);
    float4* op = (float4*)(av + (size_t)row * SS);
    int t = threadIdx.x;
#pragma unroll
    for (int q = 0; q < 2; ++q) {
        int i = t + q * 256;
        float4 h = hp[i], l = lp[i];
        op[i] = make_float4((h.x + l.x) * inv, (h.y + l.y) * inv,
                            (h.z + l.z) * inv, (h.w + l.w) * inv);
    }
}

// ---------------- GEMM2 (mma.sync tf32): c = (u @ memory_bank) * invsum ----------------
__global__ void __launch_bounds__(256) k_gemm2_mma() {
    extern __shared__ char smem[];
    const int bz = blockIdx.z, t0 = blockIdx.y * 128, n0 = blockIdx.x * 128;

    float acc[4][4][4];
    tc_loop(smem,
            g_align + (size_t)(bz * TT + t0) * SS, g_ulo + (size_t)(bz * TT + t0) * SS, SS,
            g_mbthi + ((size_t)bz * DD + n0) * SS, g_mbtlo + ((size_t)bz * DD + n0) * SS, SS,
            SS / CH_K, acc);

    const int tid = threadIdx.x, lane = tid & 31, wid = tid >> 5;
    const int wm = wid >> 2, wn = wid & 3, g = lane >> 2, tg = lane & 3;

#pragma unroll
    for (int mt = 0; mt < 4; ++mt) {
#pragma unroll
        for (int h = 0; h < 2; ++h) {
            int row = wm * 64 + mt * 16 + h * 8 + g;
            float inv = g_invsum[bz * TT + t0 + row];
            float* orow = g_c + (size_t)(bz * TT + t0 + row) * DD + n0;
#pragma unroll
            for (int nt = 0; nt < 4; ++nt) {
                int col = wn * 32 + nt * 8 + tg * 2;
                *(float2*)(orow + col) = make_float2(acc[mt][nt][h * 2 + 0] * inv,
                                                     acc[mt][nt][h * 2 + 1] * inv);
            }
        }
    }
}

// ---------------- GEMM3 (FFMA2): attn_h = tanh([c, source] @ W_out) ----------------
__device__ __forceinline__ void mma_step(const float* __restrict__ asrow,
                                         const float* __restrict__ bsrow,
                                         int ty8, int tx8,
                                         unsigned long long acc[8][4]) {
    float4 a0 = *(const float4*)(asrow + ty8);
    float4 a1 = *(const float4*)(asrow + ty8 + 4);
    unsigned long long a[8] = {fdup(a0.x), fdup(a0.y), fdup(a0.z), fdup(a0.w),
                               fdup(a1.x), fdup(a1.y), fdup(a1.z), fdup(a1.w)};
    const unsigned long long* bp = (const unsigned long long*)(bsrow + tx8);
    unsigned long long b0 = bp[0], b1 = bp[1], b2 = bp[2], b3 = bp[3];
#pragma unroll
    for (int i = 0; i < 8; ++i) {
        ffma2(acc[i][0], a[i], b0);
        ffma2(acc[i][1], a[i], b1);
        ffma2(acc[i][2], a[i], b2);
        ffma2(acc[i][3], a[i], b3);
    }
}

__global__ void __launch_bounds__(256) k_gemm3(const float* __restrict__ src,
                                               const float* __restrict__ W,
                                               float* __restrict__ outh) {
    __shared__ __align__(16) float As[2][16][132];
    __shared__ __align__(16) float Bs[2][16][132];

    const int tid = threadIdx.x;
    const int tx = tid & 15, ty = tid >> 4;
    const int m0 = blockIdx.y * 128;
    const int n0 = blockIdx.x * 128;

    const int row0 = tid >> 2;
    const int c4   = (tid & 3) * 4;
    const int r2_0 = tid >> 5;
    const int c2   = (tid & 31) * 4;

    float4 pa[2], pb[2];
#pragma unroll
    for (int l = 0; l < 2; ++l) {
        int row = row0 + l * 64;
        pa[l] = *(const float4*)(g_c + (size_t)(m0 + row) * DD + c4);
        int r2 = r2_0 + l * 8;
        pb[l] = *(const float4*)(W + (size_t)r2 * DD + n0 + c2);
    }
#pragma unroll
    for (int l = 0; l < 2; ++l) {
        int row = row0 + l * 64;
        As[0][c4 + 0][row] = pa[l].x; As[0][c4 + 1][row] = pa[l].y;
        As[0][c4 + 2][row] = pa[l].z; As[0][c4 + 3][row] = pa[l].w;
        int r2 = r2_0 + l * 8;
        *(float4*)&Bs[0][r2][c2] = pb[l];
    }
    __syncthreads();

    unsigned long long acc[8][4];
#pragma unroll
    for (int i = 0; i < 8; ++i)
#pragma unroll
        for (int j = 0; j < 4; ++j) acc[i][j] = 0ull;

    for (int kt = 0; kt < (2 * DD) / 16; ++kt) {
        int buf = kt & 1;
        if (kt < (2 * DD) / 16 - 1) {
            int k0 = (kt + 1) * 16;
#pragma unroll
            for (int l = 0; l < 2; ++l) {
                int row = row0 + l * 64;
                int m = m0 + row;
                int kg = k0 + c4;
                const float* ap = (kg < DD) ? (g_c + (size_t)m * DD + kg)
                                            : (src + (size_t)m * DD + (kg - DD));
                pa[l] = *(const float4*)ap;
                int r2 = r2_0 + l * 8;
                pb[l] = *(const float4*)(W + (size_t)(k0 + r2) * DD + n0 + c2);
            }
        }
#pragma unroll
        for (int k = 0; k < 16; ++k)
            mma_step(&As[buf][k][0], &Bs[buf][k][0], ty * 8, tx * 8, acc);
        if (kt < (2 * DD) / 16 - 1) {
            int nb = buf ^ 1;
#pragma unroll
            for (int l = 0; l < 2; ++l) {
                int row = row0 + l * 64;
                As[nb][c4 + 0][row] = pa[l].x; As[nb][c4 + 1][row] = pa[l].y;
                As[nb][c4 + 2][row] = pa[l].z; As[nb][c4 + 3][row] = pa[l].w;
                int r2 = r2_0 + l * 8;
                *(float4*)&Bs[nb][r2][c2] = pb[l];
            }
        }
        __syncthreads();
    }

#pragma unroll
    for (int i = 0; i < 8; ++i) {
        int m = m0 + ty * 8 + i;
        float v[8];
#pragma unroll
        for (int j = 0; j < 4; ++j) { v[2 * j] = lo32(acc[i][j]); v[2 * j + 1] = hi32(acc[i][j]); }
#pragma unroll
        for (int jj = 0; jj < 8; ++jj) v[jj] = tanhf(v[jj]);
        float4* op = (float4*)(outh + (size_t)m * DD + n0 + tx * 8);
        op[0] = make_float4(v[0], v[1], v[2], v[3]);
        op[1] = make_float4(v[4], v[5], v[6], v[7]);
    }
}

// ---------------- launch ----------------
extern "C" void kernel_launch(void* const* d_in, const int* in_sizes, int n_in,
                              void* d_out, int out_size) {
    const float* src  = (const float*)d_in[0];      // [B,T,D]
    const float* mb   = (const float*)d_in[1];      // [B,S,D]
    const float* W    = (const float*)d_in[2];      // [2D,D]
    const int*   lens = (const int*)d_in[3];        // [B] (int32 or int64; decoded in-kernel)

    float* outh = (float*)d_out;                    // attn_h   [B,T,D]
    float* av   = outh + (size_t)BB * TT * DD;      // align_vectors [B,T,S]

    cudaFuncSetAttribute(k_gemm1_mma, cudaFuncAttributeMaxDynamicSharedMemorySize, GSM_TOTAL);
    cudaFuncSetAttribute(k_gemm2_mma, cudaFuncAttributeMaxDynamicSharedMemorySize, GSM_TOTAL);

    float* srchi; cudaGetSymbolAddress((void**)&srchi, g_srchi);
    float* srclo; cudaGetSymbolAddress((void**)&srclo, g_srclo);
    float* mbhi;  cudaGetSymbolAddress((void**)&mbhi,  g_mbhi);
    float* mblo;  cudaGetSymbolAddress((void**)&mblo,  g_mblo);

    k_init<<<(BB * TT + 255) / 256, 256>>>();
    {
        int n4 = (BB * TT * DD) / 4;
        k_split<<<(n4 + 255) / 256, 256>>>((const float4*)src, (float4*)srchi, (float4*)srclo, n4);
    }
    {
        int n4 = (BB * SS * DD) / 4;
        k_split<<<(n4 + 255) / 256, 256>>>((const float4*)mb, (float4*)mbhi, (float4*)mblo, n4);
    }
    k_tsplit<<<dim3(SS / 32, DD / 32, BB), 256>>>(mb);

    k_gemm1_mma<<<dim3(SS / 128, TT / 128, BB), 256, GSM_TOTAL>>>(lens);

    k_colsum<<<dim3(SS / 256, NCHUNK, BB), 256>>>();
    k_scan<<<(BB * SS + 255) / 256, 256>>>();
    k_phasec<<<dim3(SS / 256, NCHUNK, BB), 256>>>();
    k_rowsum<<<(BB * TT + 255) / 256, 256>>>();
    k_norm<<<BB * TT, 256>>>(av);

    k_gemm2_mma<<<dim3(DD / 128, TT / 128, BB), 256, GSM_TOTAL>>>();
    k_gemm3<<<dim3(DD / 128, (BB * TT) / 128, 1), 256>>>(src, W, outh);
}